// round 7
// baseline (speedup 1.0000x reference)
#include <cuda_runtime.h>
#include <cstdint>

#define T_DIM 256
#define B_DIM 128
#define DIN 20
#define H_DIM 1024
#define OUT_DIM 1095
#define L_DIM 3
#define M_ALL (T_DIM * B_DIM)   // 32768
#define N_SRU (3 * H_DIM)       // 3072
#define N3PAD 1152

// ---------------- scratch ----------------
__device__ float g_h[(size_t)M_ALL * H_DIM];
__device__ float g_U[(size_t)M_ALL * N_SRU];
__device__ float g_WT[(size_t)L_DIM * N_SRU * H_DIM];
__device__ float g_W3T[(size_t)N3PAD * H_DIM];

__device__ __forceinline__ uint32_t f2tf32(float v) {
    uint32_t u;
    asm("cvt.rna.tf32.f32 %0, %1;" : "=r"(u) : "f"(v));
    return u;
}
__device__ __forceinline__ float f2tf32f(float v) { return __uint_as_float(f2tf32(v)); }

__device__ __forceinline__ uint32_t smem_u32(const void* p) {
    uint32_t a;
    asm("{ .reg .u64 t; cvta.to.shared.u64 t, %1; cvt.u32.u64 %0, t; }" : "=r"(a) : "l"(p));
    return a;
}
__device__ __forceinline__ void cpa16(uint32_t dst, const void* src) {
    asm volatile("cp.async.cg.shared.global [%0], [%1], 16;" :: "r"(dst), "l"(src) : "memory");
}
#define CPA_COMMIT() asm volatile("cp.async.commit_group;" ::: "memory")
#define CPA_WAIT1() asm volatile("cp.async.wait_group 1;" ::: "memory")

__device__ __forceinline__ void ldsm4(uint32_t& r0, uint32_t& r1, uint32_t& r2, uint32_t& r3,
                                      uint32_t addr) {
    asm volatile("ldmatrix.sync.aligned.m8n8.x4.shared.b16 {%0,%1,%2,%3}, [%4];"
                 : "=r"(r0), "=r"(r1), "=r"(r2), "=r"(r3) : "r"(addr));
}

// ---------------------------------------------------------------------------
// Prep: WT[n][k] = tf32(W[k][n]) for n < N else 0
// ---------------------------------------------------------------------------
__global__ void wtransT_kernel(const float* __restrict__ W, float* __restrict__ WT,
                               int N, int Npad) {
    __shared__ float tile[32][33];
    int n0 = blockIdx.x * 32, k0 = blockIdx.y * 32;
#pragma unroll
    for (int i = 0; i < 4; i++) {
        int k = k0 + threadIdx.y + i * 8;
        int n = n0 + threadIdx.x;
        tile[threadIdx.y + i * 8][threadIdx.x] = (n < N) ? W[(size_t)k * N + n] : 0.0f;
    }
    __syncthreads();
#pragma unroll
    for (int i = 0; i < 4; i++) {
        int n = n0 + threadIdx.y + i * 8;
        if (n < Npad)
            WT[(size_t)n * H_DIM + k0 + threadIdx.x] = f2tf32f(tile[threadIdx.x][threadIdx.y + i * 8]);
    }
}

// ---------------------------------------------------------------------------
// Dense1
// ---------------------------------------------------------------------------
__global__ void dense1_kernel(const float* __restrict__ x,
                              const float* __restrict__ W1,
                              const float* __restrict__ b1,
                              float* __restrict__ h) {
    int row = blockIdx.x;
    __shared__ float xs[DIN];
    if (threadIdx.x < DIN) xs[threadIdx.x] = x[(size_t)row * DIN + threadIdx.x];
    __syncthreads();
    for (int j = threadIdx.x; j < H_DIM; j += blockDim.x) {
        float acc = b1[j];
#pragma unroll
        for (int k = 0; k < DIN; k++) acc += xs[k] * W1[k * H_DIM + j];
        h[(size_t)row * H_DIM + j] = f2tf32f(acc);
    }
}

// ---------------------------------------------------------------------------
// TF32 GEMM: C[M,N] = A[M,1024] @ BT[N,1024]^T (+bias)
// CTA 128x128, 8 warps (4M x 2N), warp 32x64. BK=64 per stage, 3 stages,
// ONE __syncthreads per iteration. cp.async + ldmatrix.x4, XOR swizzle.
// ---------------------------------------------------------------------------
#define BK64 64
#define ROWB 256                 // bytes per smem row (64 f32)
#define STG_A (128 * ROWB)       // 32 KB
#define STG_SZ (2 * STG_A)       // 64 KB
#define NSTG 3
#define NTIL (H_DIM / BK64)      // 16

template <bool GUARD_N>
__global__ __launch_bounds__(256) void tf32_gemm(
    const float* __restrict__ A, const float* __restrict__ BT,
    float* __restrict__ C, int ldC, int Nvalid, const float* __restrict__ bias) {
    extern __shared__ char smem[];
    const uint32_t sbase = smem_u32(smem);
    const int tid = threadIdx.x;
    const int lane = tid & 31;
    const int warp = tid >> 5;
    const int wm = warp >> 1;
    const int wn = warp & 1;

    // loader: row = tid>>1 (0..127), chunks c = (tid&1)*8 + j  (16B chunks)
    const int ldR = tid >> 1;
    const int ldC0 = (tid & 1) * 8;
    const float* Ag = A + ((size_t)blockIdx.y * 128 + ldR) * H_DIM;
    const float* Bg = BT + ((size_t)blockIdx.x * 128 + ldR) * H_DIM;

    // ldmatrix lane constants
    const int mat = lane >> 3;
    const int mrow = lane & 7;
    const int rowInMat = 8 * (mat & 1) + mrow;
    const int matHalf = mat >> 1;

    float acc[2][8][4];
#pragma unroll
    for (int mi = 0; mi < 2; mi++)
#pragma unroll
        for (int ni = 0; ni < 8; ni++)
#pragma unroll
            for (int j = 0; j < 4; j++) acc[mi][ni][j] = 0.0f;

    auto issue_stage = [&](int t) {
        if (t < NTIL) {
            uint32_t st = sbase + (uint32_t)(t % NSTG) * STG_SZ;
            const float* a = Ag + t * BK64;
            const float* b = Bg + t * BK64;
#pragma unroll
            for (int j = 0; j < 8; j++) {
                int c = ldC0 + j;
                uint32_t off = (uint32_t)ldR * ROWB + (uint32_t)((c ^ (ldR & 7)) << 4);
                cpa16(st + off, a + c * 4);
                cpa16(st + STG_A + off, b + c * 4);
            }
        }
        CPA_COMMIT();
    };

    issue_stage(0);
    issue_stage(1);

    for (int t = 0; t < NTIL; t++) {
        CPA_WAIT1();
        __syncthreads();
        issue_stage(t + 2);

        const uint32_t stA = sbase + (uint32_t)(t % NSTG) * STG_SZ;
        const uint32_t stB = stA + STG_A;

#pragma unroll
        for (int kk = 0; kk < 8; kk++) {
            const int chunk = kk * 2 + matHalf;
            const uint32_t swoff = (uint32_t)((chunk ^ mrow) << 4);
            uint4 af[2];
#pragma unroll
            for (int mi = 0; mi < 2; mi++) {
                int row = wm * 32 + mi * 16 + rowInMat;
                ldsm4(af[mi].x, af[mi].y, af[mi].z, af[mi].w,
                      stA + (uint32_t)row * ROWB + swoff);
            }
            uint4 bf4[4];
#pragma unroll
            for (int g = 0; g < 4; g++) {
                int row = wn * 64 + g * 16 + rowInMat;
                ldsm4(bf4[g].x, bf4[g].y, bf4[g].z, bf4[g].w,
                      stB + (uint32_t)row * ROWB + swoff);
            }
#pragma unroll
            for (int mi = 0; mi < 2; mi++)
#pragma unroll
                for (int g = 0; g < 4; g++) {
                    asm volatile(
                        "mma.sync.aligned.m16n8k8.row.col.f32.tf32.tf32.f32 "
                        "{%0,%1,%2,%3}, {%4,%5,%6,%7}, {%8,%9}, {%0,%1,%2,%3};\n"
                        : "+f"(acc[mi][2 * g][0]), "+f"(acc[mi][2 * g][1]),
                          "+f"(acc[mi][2 * g][2]), "+f"(acc[mi][2 * g][3])
                        : "r"(af[mi].x), "r"(af[mi].y), "r"(af[mi].z), "r"(af[mi].w),
                          "r"(bf4[g].x), "r"(bf4[g].z));
                    asm volatile(
                        "mma.sync.aligned.m16n8k8.row.col.f32.tf32.tf32.f32 "
                        "{%0,%1,%2,%3}, {%4,%5,%6,%7}, {%8,%9}, {%0,%1,%2,%3};\n"
                        : "+f"(acc[mi][2 * g + 1][0]), "+f"(acc[mi][2 * g + 1][1]),
                          "+f"(acc[mi][2 * g + 1][2]), "+f"(acc[mi][2 * g + 1][3])
                        : "r"(af[mi].x), "r"(af[mi].y), "r"(af[mi].z), "r"(af[mi].w),
                          "r"(bf4[g].y), "r"(bf4[g].w));
                }
        }
    }

    // epilogue
    const int gr = lane >> 2;
    const int gc = (lane & 3) * 2;
#pragma unroll
    for (int mi = 0; mi < 2; mi++) {
        int r0 = blockIdx.y * 128 + wm * 32 + mi * 16 + gr;
#pragma unroll
        for (int ni = 0; ni < 8; ni++) {
            int c0 = blockIdx.x * 128 + wn * 64 + ni * 8 + gc;
            float b0 = 0.0f, b1 = 0.0f;
            if (bias) {
                if (!GUARD_N || c0 < Nvalid) b0 = bias[c0];
                if (!GUARD_N || c0 + 1 < Nvalid) b1 = bias[c0 + 1];
            }
            float* Cp0 = C + (size_t)r0 * ldC + c0;
            float* Cp1 = C + (size_t)(r0 + 8) * ldC + c0;
            if (!GUARD_N || c0 < Nvalid) {
                Cp0[0] = acc[mi][ni][0] + b0;
                Cp1[0] = acc[mi][ni][2] + b0;
            }
            if (!GUARD_N || c0 + 1 < Nvalid) {
                Cp0[1] = acc[mi][ni][1] + b1;
                Cp1[1] = acc[mi][ni][3] + b1;
            }
        }
    }
}

// ---------------------------------------------------------------------------
// SRU scan
// ---------------------------------------------------------------------------
__global__ void sru_scan_kernel(const float* __restrict__ U,
                                float* __restrict__ h,
                                const float* __restrict__ bf,
                                const float* __restrict__ br,
                                float* __restrict__ c_out) {
    int idx = blockIdx.x * blockDim.x + threadIdx.x;
    int b = idx / H_DIM;
    int hh = idx - b * H_DIM;
    float bfv = bf[hh];
    float brv = br[hh];
    float c = 0.0f;

    const float* Ub = U + (size_t)b * N_SRU + hh;
    float* hb = h + (size_t)b * H_DIM + hh;

    for (int t = 0; t < T_DIM; t++) {
        const float* Ut = Ub + (size_t)t * B_DIM * N_SRU;
        float z = Ut[0];
        float fp = Ut[H_DIM];
        float rp = Ut[2 * H_DIM];
        float f = 1.0f / (1.0f + __expf(-(fp + bfv)));
        float r = 1.0f / (1.0f + __expf(-(rp + brv)));
        c = f * c + (1.0f - f) * z;
        float* hp = hb + (size_t)t * B_DIM * H_DIM;
        float hin = *hp;
        *hp = f2tf32f(r * c + (1.0f - r) * hin);
    }
    c_out[idx] = c;
}

// ---------------------------------------------------------------------------
// Launch
// ---------------------------------------------------------------------------
extern "C" void kernel_launch(void* const* d_in, const int* in_sizes, int n_in,
                              void* d_out, int out_size) {
    const float* x     = (const float*)d_in[0];
    const float* W1    = (const float*)d_in[2];
    const float* b1    = (const float*)d_in[3];
    const float* W_sru = (const float*)d_in[4];
    const float* bf    = (const float*)d_in[5];
    const float* br    = (const float*)d_in[6];
    const float* W3    = (const float*)d_in[7];
    const float* b3    = (const float*)d_in[8];
    float* out = (float*)d_out;

    float *h_buf, *U_buf, *WT, *W3T;
    cudaGetSymbolAddress((void**)&h_buf, g_h);
    cudaGetSymbolAddress((void**)&U_buf, g_U);
    cudaGetSymbolAddress((void**)&WT, g_WT);
    cudaGetSymbolAddress((void**)&W3T, g_W3T);

    const int smemSz = NSTG * STG_SZ;   // 192 KB
    cudaFuncSetAttribute(tf32_gemm<false>, cudaFuncAttributeMaxDynamicSharedMemorySize, smemSz);
    cudaFuncSetAttribute(tf32_gemm<true>, cudaFuncAttributeMaxDynamicSharedMemorySize, smemSz);

    {
        dim3 blk(32, 8);
        for (int l = 0; l < L_DIM; l++) {
            dim3 grd(N_SRU / 32, H_DIM / 32);
            wtransT_kernel<<<grd, blk>>>(W_sru + (size_t)l * H_DIM * N_SRU,
                                         WT + (size_t)l * N_SRU * H_DIM, N_SRU, N_SRU);
        }
        dim3 grd3(N3PAD / 32, H_DIM / 32);
        wtransT_kernel<<<grd3, blk>>>(W3, W3T, OUT_DIM, N3PAD);
    }

    dense1_kernel<<<M_ALL, 256>>>(x, W1, b1, h_buf);

    float* c_base = out + (size_t)M_ALL * OUT_DIM;
    for (int l = 0; l < L_DIM; l++) {
        dim3 grid(N_SRU / 128, M_ALL / 128);
        tf32_gemm<false><<<grid, 256, smemSz>>>(
            h_buf, WT + (size_t)l * N_SRU * H_DIM, U_buf, N_SRU, N_SRU, nullptr);
        sru_scan_kernel<<<(B_DIM * H_DIM) / 256, 256>>>(
            U_buf, h_buf, bf + l * H_DIM, br + l * H_DIM,
            c_base + (size_t)l * B_DIM * H_DIM);
    }

    dim3 grid3(N3PAD / 128, M_ALL / 128);
    tf32_gemm<true><<<grid3, 256, smemSz>>>(h_buf, W3T, out, OUT_DIM, OUT_DIM, b3);
}

// round 8
// speedup vs baseline: 1.4400x; 1.4400x over previous
#include <cuda_runtime.h>
#include <cstdint>

#define T_DIM 256
#define B_DIM 128
#define DIN 20
#define H_DIM 1024
#define OUT_DIM 1095
#define L_DIM 3
#define M_ALL (T_DIM * B_DIM)   // 32768
#define N_SRU (3 * H_DIM)       // 3072
#define N3PAD 1152

// ---------------- scratch ----------------
__device__ float g_h[(size_t)M_ALL * H_DIM];
__device__ float g_U[(size_t)M_ALL * N_SRU];
__device__ float g_WT[(size_t)L_DIM * N_SRU * H_DIM];
__device__ float g_W3T[(size_t)N3PAD * H_DIM];

__device__ __forceinline__ uint32_t f2tf32(float v) {
    uint32_t u;
    asm("cvt.rna.tf32.f32 %0, %1;" : "=r"(u) : "f"(v));
    return u;
}
__device__ __forceinline__ float f2tf32f(float v) { return __uint_as_float(f2tf32(v)); }

__device__ __forceinline__ uint32_t smem_u32(const void* p) {
    uint32_t a;
    asm("{ .reg .u64 t; cvta.to.shared.u64 t, %1; cvt.u32.u64 %0, t; }" : "=r"(a) : "l"(p));
    return a;
}
__device__ __forceinline__ void cpa16(uint32_t dst, const void* src) {
    asm volatile("cp.async.cg.shared.global [%0], [%1], 16;" :: "r"(dst), "l"(src) : "memory");
}
#define CPA_COMMIT() asm volatile("cp.async.commit_group;" ::: "memory")
#define CPA_WAIT1() asm volatile("cp.async.wait_group 1;" ::: "memory")

__device__ __forceinline__ void ldsm4(uint32_t& r0, uint32_t& r1, uint32_t& r2, uint32_t& r3,
                                      uint32_t addr) {
    asm volatile("ldmatrix.sync.aligned.m8n8.x4.shared.b16 {%0,%1,%2,%3}, [%4];"
                 : "=r"(r0), "=r"(r1), "=r"(r2), "=r"(r3) : "r"(addr));
}

// ---------------------------------------------------------------------------
// Prep: WT[n][k] = tf32(W[k][n]) for n < N else 0
// ---------------------------------------------------------------------------
__global__ void wtransT_kernel(const float* __restrict__ W, float* __restrict__ WT,
                               int N, int Npad) {
    __shared__ float tile[32][33];
    int n0 = blockIdx.x * 32, k0 = blockIdx.y * 32;
#pragma unroll
    for (int i = 0; i < 4; i++) {
        int k = k0 + threadIdx.y + i * 8;
        int n = n0 + threadIdx.x;
        tile[threadIdx.y + i * 8][threadIdx.x] = (n < N) ? W[(size_t)k * N + n] : 0.0f;
    }
    __syncthreads();
#pragma unroll
    for (int i = 0; i < 4; i++) {
        int n = n0 + threadIdx.y + i * 8;
        if (n < Npad)
            WT[(size_t)n * H_DIM + k0 + threadIdx.x] = f2tf32f(tile[threadIdx.x][threadIdx.y + i * 8]);
    }
}

// ---------------------------------------------------------------------------
// Dense1
// ---------------------------------------------------------------------------
__global__ void dense1_kernel(const float* __restrict__ x,
                              const float* __restrict__ W1,
                              const float* __restrict__ b1,
                              float* __restrict__ h) {
    int row = blockIdx.x;
    __shared__ float xs[DIN];
    if (threadIdx.x < DIN) xs[threadIdx.x] = x[(size_t)row * DIN + threadIdx.x];
    __syncthreads();
    for (int j = threadIdx.x; j < H_DIM; j += blockDim.x) {
        float acc = b1[j];
#pragma unroll
        for (int k = 0; k < DIN; k++) acc += xs[k] * W1[k * H_DIM + j];
        h[(size_t)row * H_DIM + j] = f2tf32f(acc);
    }
}

// ---------------------------------------------------------------------------
// TF32 GEMM: C[M,N] = A[M,1024] @ BT[N,1024]^T (+bias)
// CTA 128x128, 8 warps (4M x 2N), warp 32x64. BK=32, 3 stages (96 KB ->
// 2 CTAs/SM), ONE __syncthreads per iteration. cp.async + ldmatrix.x4,
// chunk-XOR swizzle.
// ---------------------------------------------------------------------------
#define BK32 32
#define ROWB 128                 // bytes per smem row (32 f32)
#define STG_A (128 * ROWB)       // 16 KB
#define STG_SZ (2 * STG_A)       // 32 KB
#define NSTG 3
#define NTIL (H_DIM / BK32)      // 32

template <bool GUARD_N>
__global__ __launch_bounds__(256) void tf32_gemm(
    const float* __restrict__ A, const float* __restrict__ BT,
    float* __restrict__ C, int ldC, int Nvalid, const float* __restrict__ bias) {
    extern __shared__ char smem[];
    const uint32_t sbase = smem_u32(smem);
    const int tid = threadIdx.x;
    const int lane = tid & 31;
    const int warp = tid >> 5;
    const int wm = warp >> 1;
    const int wn = warp & 1;

    // loader: row = tid>>1 (0..127), chunks c = (tid&1)*4 + j  (16B chunks)
    const int ldR = tid >> 1;
    const int ldC0 = (tid & 1) * 4;
    const float* Ag = A + ((size_t)blockIdx.y * 128 + ldR) * H_DIM;
    const float* Bg = BT + ((size_t)blockIdx.x * 128 + ldR) * H_DIM;

    // ldmatrix lane constants
    const int mat = lane >> 3;
    const int mrow = lane & 7;
    const int rowInMat = 8 * (mat & 1) + mrow;
    const int matHalf = mat >> 1;

    float acc[2][8][4];
#pragma unroll
    for (int mi = 0; mi < 2; mi++)
#pragma unroll
        for (int ni = 0; ni < 8; ni++)
#pragma unroll
            for (int j = 0; j < 4; j++) acc[mi][ni][j] = 0.0f;

    auto issue_stage = [&](int t) {
        if (t < NTIL) {
            uint32_t st = sbase + (uint32_t)(t % NSTG) * STG_SZ;
            const float* a = Ag + t * BK32;
            const float* b = Bg + t * BK32;
#pragma unroll
            for (int j = 0; j < 4; j++) {
                int c = ldC0 + j;
                uint32_t off = (uint32_t)ldR * ROWB + (uint32_t)((c ^ (ldR & 7)) << 4);
                cpa16(st + off, a + c * 4);
                cpa16(st + STG_A + off, b + c * 4);
            }
        }
        CPA_COMMIT();
    };

    issue_stage(0);
    issue_stage(1);

    for (int t = 0; t < NTIL; t++) {
        CPA_WAIT1();
        __syncthreads();
        issue_stage(t + 2);   // buffer (t+2)%3 == (t-1)%3; readers done pre-sync

        const uint32_t stA = sbase + (uint32_t)(t % NSTG) * STG_SZ;
        const uint32_t stB = stA + STG_A;

#pragma unroll
        for (int kk = 0; kk < 4; kk++) {
            const int chunk = kk * 2 + matHalf;
            const uint32_t swoff = (uint32_t)((chunk ^ mrow) << 4);
            uint4 af[2];
#pragma unroll
            for (int mi = 0; mi < 2; mi++) {
                int row = wm * 32 + mi * 16 + rowInMat;
                ldsm4(af[mi].x, af[mi].y, af[mi].z, af[mi].w,
                      stA + (uint32_t)row * ROWB + swoff);
            }
            uint4 bf4[4];
#pragma unroll
            for (int g = 0; g < 4; g++) {
                int row = wn * 64 + g * 16 + rowInMat;
                ldsm4(bf4[g].x, bf4[g].y, bf4[g].z, bf4[g].w,
                      stB + (uint32_t)row * ROWB + swoff);
            }
#pragma unroll
            for (int mi = 0; mi < 2; mi++)
#pragma unroll
                for (int g = 0; g < 4; g++) {
                    asm volatile(
                        "mma.sync.aligned.m16n8k8.row.col.f32.tf32.tf32.f32 "
                        "{%0,%1,%2,%3}, {%4,%5,%6,%7}, {%8,%9}, {%0,%1,%2,%3};\n"
                        : "+f"(acc[mi][2 * g][0]), "+f"(acc[mi][2 * g][1]),
                          "+f"(acc[mi][2 * g][2]), "+f"(acc[mi][2 * g][3])
                        : "r"(af[mi].x), "r"(af[mi].y), "r"(af[mi].z), "r"(af[mi].w),
                          "r"(bf4[g].x), "r"(bf4[g].z));
                    asm volatile(
                        "mma.sync.aligned.m16n8k8.row.col.f32.tf32.tf32.f32 "
                        "{%0,%1,%2,%3}, {%4,%5,%6,%7}, {%8,%9}, {%0,%1,%2,%3};\n"
                        : "+f"(acc[mi][2 * g + 1][0]), "+f"(acc[mi][2 * g + 1][1]),
                          "+f"(acc[mi][2 * g + 1][2]), "+f"(acc[mi][2 * g + 1][3])
                        : "r"(af[mi].x), "r"(af[mi].y), "r"(af[mi].z), "r"(af[mi].w),
                          "r"(bf4[g].y), "r"(bf4[g].w));
                }
        }
    }

    // epilogue
    const int gr = lane >> 2;
    const int gc = (lane & 3) * 2;
#pragma unroll
    for (int mi = 0; mi < 2; mi++) {
        int r0 = blockIdx.y * 128 + wm * 32 + mi * 16 + gr;
#pragma unroll
        for (int ni = 0; ni < 8; ni++) {
            int c0 = blockIdx.x * 128 + wn * 64 + ni * 8 + gc;
            float b0 = 0.0f, b1 = 0.0f;
            if (bias) {
                if (!GUARD_N || c0 < Nvalid) b0 = bias[c0];
                if (!GUARD_N || c0 + 1 < Nvalid) b1 = bias[c0 + 1];
            }
            float* Cp0 = C + (size_t)r0 * ldC + c0;
            float* Cp1 = C + (size_t)(r0 + 8) * ldC + c0;
            if (!GUARD_N || c0 < Nvalid) {
                Cp0[0] = acc[mi][ni][0] + b0;
                Cp1[0] = acc[mi][ni][2] + b0;
            }
            if (!GUARD_N || c0 + 1 < Nvalid) {
                Cp0[1] = acc[mi][ni][1] + b1;
                Cp1[1] = acc[mi][ni][3] + b1;
            }
        }
    }
}

// ---------------------------------------------------------------------------
// SRU scan
// ---------------------------------------------------------------------------
__global__ void sru_scan_kernel(const float* __restrict__ U,
                                float* __restrict__ h,
                                const float* __restrict__ bf,
                                const float* __restrict__ br,
                                float* __restrict__ c_out) {
    int idx = blockIdx.x * blockDim.x + threadIdx.x;
    int b = idx / H_DIM;
    int hh = idx - b * H_DIM;
    float bfv = bf[hh];
    float brv = br[hh];
    float c = 0.0f;

    const float* Ub = U + (size_t)b * N_SRU + hh;
    float* hb = h + (size_t)b * H_DIM + hh;

    for (int t = 0; t < T_DIM; t++) {
        const float* Ut = Ub + (size_t)t * B_DIM * N_SRU;
        float z = Ut[0];
        float fp = Ut[H_DIM];
        float rp = Ut[2 * H_DIM];
        float f = 1.0f / (1.0f + __expf(-(fp + bfv)));
        float r = 1.0f / (1.0f + __expf(-(rp + brv)));
        c = f * c + (1.0f - f) * z;
        float* hp = hb + (size_t)t * B_DIM * H_DIM;
        float hin = *hp;
        *hp = f2tf32f(r * c + (1.0f - r) * hin);
    }
    c_out[idx] = c;
}

// ---------------------------------------------------------------------------
// Launch
// ---------------------------------------------------------------------------
extern "C" void kernel_launch(void* const* d_in, const int* in_sizes, int n_in,
                              void* d_out, int out_size) {
    const float* x     = (const float*)d_in[0];
    const float* W1    = (const float*)d_in[2];
    const float* b1    = (const float*)d_in[3];
    const float* W_sru = (const float*)d_in[4];
    const float* bf    = (const float*)d_in[5];
    const float* br    = (const float*)d_in[6];
    const float* W3    = (const float*)d_in[7];
    const float* b3    = (const float*)d_in[8];
    float* out = (float*)d_out;

    float *h_buf, *U_buf, *WT, *W3T;
    cudaGetSymbolAddress((void**)&h_buf, g_h);
    cudaGetSymbolAddress((void**)&U_buf, g_U);
    cudaGetSymbolAddress((void**)&WT, g_WT);
    cudaGetSymbolAddress((void**)&W3T, g_W3T);

    const int smemSz = NSTG * STG_SZ;   // 96 KB -> 2 CTAs/SM
    cudaFuncSetAttribute(tf32_gemm<false>, cudaFuncAttributeMaxDynamicSharedMemorySize, smemSz);
    cudaFuncSetAttribute(tf32_gemm<true>, cudaFuncAttributeMaxDynamicSharedMemorySize, smemSz);

    {
        dim3 blk(32, 8);
        for (int l = 0; l < L_DIM; l++) {
            dim3 grd(N_SRU / 32, H_DIM / 32);
            wtransT_kernel<<<grd, blk>>>(W_sru + (size_t)l * H_DIM * N_SRU,
                                         WT + (size_t)l * N_SRU * H_DIM, N_SRU, N_SRU);
        }
        dim3 grd3(N3PAD / 32, H_DIM / 32);
        wtransT_kernel<<<grd3, blk>>>(W3, W3T, OUT_DIM, N3PAD);
    }

    dense1_kernel<<<M_ALL, 256>>>(x, W1, b1, h_buf);

    float* c_base = out + (size_t)M_ALL * OUT_DIM;
    for (int l = 0; l < L_DIM; l++) {
        dim3 grid(N_SRU / 128, M_ALL / 128);
        tf32_gemm<false><<<grid, 256, smemSz>>>(
            h_buf, WT + (size_t)l * N_SRU * H_DIM, U_buf, N_SRU, N_SRU, nullptr);
        sru_scan_kernel<<<(B_DIM * H_DIM) / 256, 256>>>(
            U_buf, h_buf, bf + l * H_DIM, br + l * H_DIM,
            c_base + (size_t)l * B_DIM * H_DIM);
    }

    dim3 grid3(N3PAD / 128, M_ALL / 128);
    tf32_gemm<true><<<grid3, 256, smemSz>>>(h_buf, W3T, out, OUT_DIM, OUT_DIM, b3);
}

// round 9
// speedup vs baseline: 1.8013x; 1.2509x over previous
#include <cuda_runtime.h>
#include <cstdint>

#define T_DIM 256
#define B_DIM 128
#define DIN 20
#define H_DIM 1024
#define OUT_DIM 1095
#define L_DIM 3
#define M_ALL (T_DIM * B_DIM)   // 32768
#define N_SRU (3 * H_DIM)       // 3072
#define N3PAD 1152
#define K8CNT (H_DIM / 8)       // 128 k8-blocks

// ---------------- scratch ----------------
__device__ float g_h[(size_t)M_ALL * H_DIM];
__device__ float g_U[(size_t)M_ALL * N_SRU];
// B fragments: [n8][k8][lane] x uint2 (b0,b1) — same total size as W
__device__ float g_WT[(size_t)L_DIM * N_SRU * H_DIM];
__device__ float g_W3T[(size_t)N3PAD * H_DIM];

__device__ __forceinline__ uint32_t f2tf32(float v) {
    uint32_t u;
    asm("cvt.rna.tf32.f32 %0, %1;" : "=r"(u) : "f"(v));
    return u;
}
__device__ __forceinline__ float f2tf32f(float v) { return __uint_as_float(f2tf32(v)); }

__device__ __forceinline__ uint32_t smem_u32(const void* p) {
    uint32_t a;
    asm("{ .reg .u64 t; cvta.to.shared.u64 t, %1; cvt.u32.u64 %0, t; }" : "=r"(a) : "l"(p));
    return a;
}
__device__ __forceinline__ void cpa16(uint32_t dst, const void* src) {
    asm volatile("cp.async.cg.shared.global [%0], [%1], 16;" :: "r"(dst), "l"(src) : "memory");
}
#define CPA_COMMIT() asm volatile("cp.async.commit_group;" ::: "memory")
#define CPA_WAIT1() asm volatile("cp.async.wait_group 1;" ::: "memory")

__device__ __forceinline__ void ldsm4(uint32_t& r0, uint32_t& r1, uint32_t& r2, uint32_t& r3,
                                      uint32_t addr) {
    asm volatile("ldmatrix.sync.aligned.m8n8.x4.shared.b16 {%0,%1,%2,%3}, [%4];"
                 : "=r"(r0), "=r"(r1), "=r"(r2), "=r"(r3) : "r"(addr));
}

// ---------------------------------------------------------------------------
// Prep: write W [K=1024][N] into per-lane MMA B-fragment order.
// BF[((n8*K8CNT)+k8)*32 + lane] = uint2{ tf32(W[k8*8+(lane&3)][n8*8+(lane>>2)]),
//                                        tf32(W[k8*8+(lane&3)+4][ same n ]) }
// n >= N -> 0 (padding).
// ---------------------------------------------------------------------------
__global__ void wfrag_kernel(const float* __restrict__ W, uint2* __restrict__ BF,
                             int N, int N8) {
    int task = blockIdx.x * 8 + (threadIdx.x >> 5);
    int n8 = task / K8CNT;
    int k8 = task - n8 * K8CNT;
    if (n8 >= N8) return;
    int lane = threadIdx.x & 31;
    int n = n8 * 8 + (lane >> 2);
    int kq = k8 * 8 + (lane & 3);
    float b0 = 0.0f, b1 = 0.0f;
    if (n < N) {
        b0 = W[(size_t)kq * N + n];
        b1 = W[(size_t)(kq + 4) * N + n];
    }
    BF[((size_t)n8 * K8CNT + k8) * 32 + lane] = make_uint2(f2tf32(b0), f2tf32(b1));
}

// ---------------------------------------------------------------------------
// Dense1
// ---------------------------------------------------------------------------
__global__ void dense1_kernel(const float* __restrict__ x,
                              const float* __restrict__ W1,
                              const float* __restrict__ b1,
                              float* __restrict__ h) {
    int row = blockIdx.x;
    __shared__ float xs[DIN];
    if (threadIdx.x < DIN) xs[threadIdx.x] = x[(size_t)row * DIN + threadIdx.x];
    __syncthreads();
    for (int j = threadIdx.x; j < H_DIM; j += blockDim.x) {
        float acc = b1[j];
#pragma unroll
        for (int k = 0; k < DIN; k++) acc += xs[k] * W1[k * H_DIM + j];
        h[(size_t)row * H_DIM + j] = f2tf32f(acc);
    }
}

// ---------------------------------------------------------------------------
// TF32 GEMM: C[M,N] = A[M,1024] @ B (B given as fragment-ordered BF) (+bias)
// CTA 128x128, 8 warps (4M x 2N), warp 32x64.
// A: BK=32, 3 stages cp.async + ldmatrix (16 KB/stage, chunk-XOR swizzle).
// B: direct LDG.64 of pre-arranged fragments (no smem round trip).
// ---------------------------------------------------------------------------
#define BK32 32
#define ROWB 128                 // bytes per A smem row (32 f32)
#define STG_A (128 * ROWB)       // 16 KB per stage
#define NSTG 3
#define NTIL (H_DIM / BK32)      // 32

template <bool GUARD_N>
__global__ __launch_bounds__(256, 2) void tf32_gemm(
    const float* __restrict__ A, const uint2* __restrict__ BF,
    float* __restrict__ C, int ldC, int Nvalid, const float* __restrict__ bias) {
    extern __shared__ char smem[];
    const uint32_t sbase = smem_u32(smem);
    const int tid = threadIdx.x;
    const int lane = tid & 31;
    const int warp = tid >> 5;
    const int wm = warp >> 1;
    const int wn = warp & 1;

    // A loader: row = tid>>1 (0..127), chunks c = (tid&1)*4 + j  (16B chunks)
    const int ldR = tid >> 1;
    const int ldC0 = (tid & 1) * 4;
    const float* Ag = A + ((size_t)blockIdx.y * 128 + ldR) * H_DIM;

    // B fragment base for this warp: n8 block = blockIdx.x*16 + wn*8
    const uint2* Bf = BF + ((size_t)(blockIdx.x * 16 + wn * 8) * K8CNT) * 32 + lane;

    // ldmatrix lane constants (A)
    const int mat = lane >> 3;
    const int mrow = lane & 7;
    const int rowInMat = 8 * (mat & 1) + mrow;
    const int matHalf = mat >> 1;

    float acc[2][8][4];
#pragma unroll
    for (int mi = 0; mi < 2; mi++)
#pragma unroll
        for (int ni = 0; ni < 8; ni++)
#pragma unroll
            for (int j = 0; j < 4; j++) acc[mi][ni][j] = 0.0f;

    auto issue_stage = [&](int t) {
        if (t < NTIL) {
            uint32_t st = sbase + (uint32_t)(t % NSTG) * STG_A;
            const float* a = Ag + t * BK32;
#pragma unroll
            for (int j = 0; j < 4; j++) {
                int c = ldC0 + j;
                uint32_t off = (uint32_t)ldR * ROWB + (uint32_t)((c ^ (ldR & 7)) << 4);
                cpa16(st + off, a + c * 4);
            }
        }
        CPA_COMMIT();
    };

    issue_stage(0);
    issue_stage(1);

    for (int t = 0; t < NTIL; t++) {
        CPA_WAIT1();
        __syncthreads();
        issue_stage(t + 2);

        const uint32_t stA = sbase + (uint32_t)(t % NSTG) * STG_A;

#pragma unroll
        for (int kk = 0; kk < 4; kk++) {
            const int k8g = t * 4 + kk;
            // B fragments: 8 direct LDG.64 (issued first: longest latency)
            uint2 bq[8];
#pragma unroll
            for (int ni = 0; ni < 8; ni++)
                bq[ni] = Bf[((size_t)ni * K8CNT + k8g) * 32];
            // A fragments via ldmatrix
            const int chunk = kk * 2 + matHalf;
            const uint32_t swoff = (uint32_t)((chunk ^ mrow) << 4);
            uint4 af[2];
#pragma unroll
            for (int mi = 0; mi < 2; mi++) {
                int row = wm * 32 + mi * 16 + rowInMat;
                ldsm4(af[mi].x, af[mi].y, af[mi].z, af[mi].w,
                      stA + (uint32_t)row * ROWB + swoff);
            }
#pragma unroll
            for (int mi = 0; mi < 2; mi++)
#pragma unroll
                for (int ni = 0; ni < 8; ni++) {
                    asm volatile(
                        "mma.sync.aligned.m16n8k8.row.col.f32.tf32.tf32.f32 "
                        "{%0,%1,%2,%3}, {%4,%5,%6,%7}, {%8,%9}, {%0,%1,%2,%3};\n"
                        : "+f"(acc[mi][ni][0]), "+f"(acc[mi][ni][1]),
                          "+f"(acc[mi][ni][2]), "+f"(acc[mi][ni][3])
                        : "r"(af[mi].x), "r"(af[mi].y), "r"(af[mi].z), "r"(af[mi].w),
                          "r"(bq[ni].x), "r"(bq[ni].y));
                }
        }
    }

    // epilogue
    const int gr = lane >> 2;
    const int gc = (lane & 3) * 2;
#pragma unroll
    for (int mi = 0; mi < 2; mi++) {
        int r0 = blockIdx.y * 128 + wm * 32 + mi * 16 + gr;
#pragma unroll
        for (int ni = 0; ni < 8; ni++) {
            int c0 = blockIdx.x * 128 + wn * 64 + ni * 8 + gc;
            float b0 = 0.0f, b1 = 0.0f;
            if (bias) {
                if (!GUARD_N || c0 < Nvalid) b0 = bias[c0];
                if (!GUARD_N || c0 + 1 < Nvalid) b1 = bias[c0 + 1];
            }
            float* Cp0 = C + (size_t)r0 * ldC + c0;
            float* Cp1 = C + (size_t)(r0 + 8) * ldC + c0;
            if (!GUARD_N || c0 < Nvalid) {
                Cp0[0] = acc[mi][ni][0] + b0;
                Cp1[0] = acc[mi][ni][2] + b0;
            }
            if (!GUARD_N || c0 + 1 < Nvalid) {
                Cp0[1] = acc[mi][ni][1] + b1;
                Cp1[1] = acc[mi][ni][3] + b1;
            }
        }
    }
}

// ---------------------------------------------------------------------------
// SRU scan
// ---------------------------------------------------------------------------
__global__ void sru_scan_kernel(const float* __restrict__ U,
                                float* __restrict__ h,
                                const float* __restrict__ bf,
                                const float* __restrict__ br,
                                float* __restrict__ c_out) {
    int idx = blockIdx.x * blockDim.x + threadIdx.x;
    int b = idx / H_DIM;
    int hh = idx - b * H_DIM;
    float bfv = bf[hh];
    float brv = br[hh];
    float c = 0.0f;

    const float* Ub = U + (size_t)b * N_SRU + hh;
    float* hb = h + (size_t)b * H_DIM + hh;

    for (int t = 0; t < T_DIM; t++) {
        const float* Ut = Ub + (size_t)t * B_DIM * N_SRU;
        float z = Ut[0];
        float fp = Ut[H_DIM];
        float rp = Ut[2 * H_DIM];
        float f = 1.0f / (1.0f + __expf(-(fp + bfv)));
        float r = 1.0f / (1.0f + __expf(-(rp + brv)));
        c = f * c + (1.0f - f) * z;
        float* hp = hb + (size_t)t * B_DIM * H_DIM;
        float hin = *hp;
        *hp = f2tf32f(r * c + (1.0f - r) * hin);
    }
    c_out[idx] = c;
}

// ---------------------------------------------------------------------------
// Launch
// ---------------------------------------------------------------------------
extern "C" void kernel_launch(void* const* d_in, const int* in_sizes, int n_in,
                              void* d_out, int out_size) {
    const float* x     = (const float*)d_in[0];
    const float* W1    = (const float*)d_in[2];
    const float* b1    = (const float*)d_in[3];
    const float* W_sru = (const float*)d_in[4];
    const float* bf    = (const float*)d_in[5];
    const float* br    = (const float*)d_in[6];
    const float* W3    = (const float*)d_in[7];
    const float* b3    = (const float*)d_in[8];
    float* out = (float*)d_out;

    float *h_buf, *U_buf, *WTf, *W3Tf;
    cudaGetSymbolAddress((void**)&h_buf, g_h);
    cudaGetSymbolAddress((void**)&U_buf, g_U);
    cudaGetSymbolAddress((void**)&WTf, g_WT);
    cudaGetSymbolAddress((void**)&W3Tf, g_W3T);
    uint2* BF = (uint2*)WTf;
    uint2* BF3 = (uint2*)W3Tf;
    const size_t bfLayerStride = (size_t)(N_SRU / 8) * K8CNT * 32;  // uint2 elems

    const int smemSz = NSTG * STG_A;   // 48 KB
    cudaFuncSetAttribute(tf32_gemm<false>, cudaFuncAttributeMaxDynamicSharedMemorySize, smemSz);
    cudaFuncSetAttribute(tf32_gemm<true>, cudaFuncAttributeMaxDynamicSharedMemorySize, smemSz);

    // prep: W -> fragment order
    {
        const int N8 = N_SRU / 8;                  // 384
        int tasks = N8 * K8CNT;                    // 49152
        for (int l = 0; l < L_DIM; l++)
            wfrag_kernel<<<tasks / 8, 256>>>(W_sru + (size_t)l * H_DIM * N_SRU,
                                             BF + l * bfLayerStride, N_SRU, N8);
        const int N83 = N3PAD / 8;                 // 144
        wfrag_kernel<<<(N83 * K8CNT) / 8, 256>>>(W3, BF3, OUT_DIM, N83);
    }

    dense1_kernel<<<M_ALL, 256>>>(x, W1, b1, h_buf);

    float* c_base = out + (size_t)M_ALL * OUT_DIM;
    for (int l = 0; l < L_DIM; l++) {
        dim3 grid(N_SRU / 128, M_ALL / 128);
        tf32_gemm<false><<<grid, 256, smemSz>>>(
            h_buf, BF + l * bfLayerStride, U_buf, N_SRU, N_SRU, nullptr);
        sru_scan_kernel<<<(B_DIM * H_DIM) / 256, 256>>>(
            U_buf, h_buf, bf + l * H_DIM, br + l * H_DIM,
            c_base + (size_t)l * B_DIM * H_DIM);
    }

    dim3 grid3(N3PAD / 128, M_ALL / 128);
    tf32_gemm<true><<<grid3, 256, smemSz>>>(h_buf, BF3, out, OUT_DIM, OUT_DIM, b3);
}

// round 10
// speedup vs baseline: 2.2541x; 1.2514x over previous
#include <cuda_runtime.h>
#include <cstdint>

#define T_DIM 256
#define B_DIM 128
#define DIN 20
#define H_DIM 1024
#define OUT_DIM 1095
#define L_DIM 3
#define M_ALL (T_DIM * B_DIM)   // 32768
#define N_SRU (3 * H_DIM)       // 3072
#define N3PAD 1152
#define K8CNT (H_DIM / 8)       // 128
#define KPCNT (K8CNT / 2)       // 64 k8-pairs

// ---------------- scratch ----------------
__device__ float g_h[(size_t)M_ALL * H_DIM];                      // 134 MB
__device__ float g_U[(size_t)M_ALL * N_SRU];                      // 402 MB
__device__ uint4 g_Af[(size_t)(M_ALL / 16) * K8CNT * 32];         // 134 MB
__device__ float g_WT[(size_t)L_DIM * N_SRU * H_DIM];             // BF4 storage
__device__ float g_W3T[(size_t)N3PAD * H_DIM];

__device__ __forceinline__ uint32_t f2tf32(float v) {
    uint32_t u;
    asm("cvt.rna.tf32.f32 %0, %1;" : "=r"(u) : "f"(v));
    return u;
}
__device__ __forceinline__ float f2tf32f(float v) { return __uint_as_float(f2tf32(v)); }

// ---------------------------------------------------------------------------
// Prep B: W[K][N] -> fragment-pair order.
// BF[((n8*KPCNT)+kp)*32+lane] = uint4{ b0(k8=2kp), b1(k8=2kp), b0(k8=2kp+1), b1(k8=2kp+1) }
// where b0 = tf32(W[k8*8+(lane&3)][n8*8+(lane>>2)]), b1 = same with k+4.
// ---------------------------------------------------------------------------
__global__ void wfrag_kernel(const float* __restrict__ W, uint4* __restrict__ BF,
                             int N, int N8) {
    int task = blockIdx.x * 8 + (threadIdx.x >> 5);
    int n8 = task / KPCNT;
    int kp = task - n8 * KPCNT;
    if (n8 >= N8) return;
    int lane = threadIdx.x & 31;
    int n = n8 * 8 + (lane >> 2);
    int kq = kp * 16 + (lane & 3);
    float b0 = 0.0f, b1 = 0.0f, b2 = 0.0f, b3 = 0.0f;
    if (n < N) {
        b0 = W[(size_t)kq * N + n];
        b1 = W[(size_t)(kq + 4) * N + n];
        b2 = W[(size_t)(kq + 8) * N + n];
        b3 = W[(size_t)(kq + 12) * N + n];
    }
    BF[((size_t)n8 * KPCNT + kp) * 32 + lane] =
        make_uint4(f2tf32(b0), f2tf32(b1), f2tf32(b2), f2tf32(b3));
}

// ---------------------------------------------------------------------------
// Prep A: h[M][K] (already tf32-rounded bits) -> per-lane A fragments.
// Af[((m16*K8CNT)+k8)*32+lane] = uint4{ h[m16*16+gr][k8*8+gc], h[..+gr+8][gc],
//                                       h[gr][gc+4], h[gr+8][gc+4] }  (gr=lane>>2, gc=lane&3)
// Block: 64 rows x 32 cols tile via smem.
// ---------------------------------------------------------------------------
__global__ void afrag_kernel(const float* __restrict__ h, uint4* __restrict__ Af) {
    __shared__ float s[64][33];
    const int r0 = blockIdx.x * 64;
    const int c0 = blockIdx.y * 32;
    const int tid = threadIdx.x;
    const int lr = tid >> 3, lc = (tid & 7) * 4;
    {
        float4 v = *(const float4*)(h + (size_t)(r0 + lr) * H_DIM + c0 + lc);
        s[lr][lc] = v.x; s[lr][lc + 1] = v.y; s[lr][lc + 2] = v.z; s[lr][lc + 3] = v.w;
        float4 w = *(const float4*)(h + (size_t)(r0 + lr + 32) * H_DIM + c0 + lc);
        s[lr + 32][lc] = w.x; s[lr + 32][lc + 1] = w.y;
        s[lr + 32][lc + 2] = w.z; s[lr + 32][lc + 3] = w.w;
    }
    __syncthreads();
    const int warp = tid >> 5, lane = tid & 31;
    const int gr = lane >> 2, gc = lane & 3;
#pragma unroll
    for (int i = 0; i < 2; i++) {
        int sblk = warp * 2 + i;          // 0..15
        int mi = sblk >> 2, ki = sblk & 3;
        uint4 v;
        v.x = __float_as_uint(s[mi * 16 + gr][ki * 8 + gc]);
        v.y = __float_as_uint(s[mi * 16 + gr + 8][ki * 8 + gc]);
        v.z = __float_as_uint(s[mi * 16 + gr][ki * 8 + gc + 4]);
        v.w = __float_as_uint(s[mi * 16 + gr + 8][ki * 8 + gc + 4]);
        Af[((size_t)(r0 / 16 + mi) * K8CNT + (c0 / 8 + ki)) * 32 + lane] = v;
    }
}

// ---------------------------------------------------------------------------
// Dense1
// ---------------------------------------------------------------------------
__global__ void dense1_kernel(const float* __restrict__ x,
                              const float* __restrict__ W1,
                              const float* __restrict__ b1,
                              float* __restrict__ h) {
    int row = blockIdx.x;
    __shared__ float xs[DIN];
    if (threadIdx.x < DIN) xs[threadIdx.x] = x[(size_t)row * DIN + threadIdx.x];
    __syncthreads();
    for (int j = threadIdx.x; j < H_DIM; j += blockDim.x) {
        float acc = b1[j];
#pragma unroll
        for (int k = 0; k < DIN; k++) acc += xs[k] * W1[k * H_DIM + j];
        h[(size_t)row * H_DIM + j] = f2tf32f(acc);
    }
}

// ---------------------------------------------------------------------------
// TF32 GEMM, fragment-direct: C[M,N] = A @ B^T (+bias)
// CTA 128x128, 8 warps (4M x 2N), warp 32x64. No smem, no barriers:
// operands arrive as pre-packed fragments via LDG.128.
// ---------------------------------------------------------------------------
template <bool GUARD_N>
__global__ __launch_bounds__(256, 2) void tf32_gemm(
    const uint4* __restrict__ Af, const uint4* __restrict__ Bf,
    float* __restrict__ C, int ldC, int Nvalid, const float* __restrict__ bias) {
    const int tid = threadIdx.x;
    const int lane = tid & 31;
    const int warp = tid >> 5;
    const int wm = warp >> 1;
    const int wn = warp & 1;

    const uint4* Ap = Af + ((size_t)(blockIdx.y * 8 + wm * 2) * K8CNT) * 32 + lane;
    const uint4* Bp = Bf + ((size_t)(blockIdx.x * 16 + wn * 8) * KPCNT) * 32 + lane;

    float acc[2][8][4];
#pragma unroll
    for (int mi = 0; mi < 2; mi++)
#pragma unroll
        for (int ni = 0; ni < 8; ni++)
#pragma unroll
            for (int j = 0; j < 4; j++) acc[mi][ni][j] = 0.0f;

    for (int kp = 0; kp < KPCNT; kp++) {
        uint4 b4[8];
#pragma unroll
        for (int ni = 0; ni < 8; ni++)
            b4[ni] = Bp[((size_t)ni * KPCNT + kp) * 32];
        uint4 a4[2][2];
#pragma unroll
        for (int s = 0; s < 2; s++)
#pragma unroll
            for (int mi = 0; mi < 2; mi++)
                a4[s][mi] = Ap[((size_t)mi * K8CNT + 2 * kp + s) * 32];

#pragma unroll
        for (int s = 0; s < 2; s++)
#pragma unroll
            for (int mi = 0; mi < 2; mi++)
#pragma unroll
                for (int ni = 0; ni < 8; ni++) {
                    uint32_t bx = s ? b4[ni].z : b4[ni].x;
                    uint32_t by = s ? b4[ni].w : b4[ni].y;
                    asm volatile(
                        "mma.sync.aligned.m16n8k8.row.col.f32.tf32.tf32.f32 "
                        "{%0,%1,%2,%3}, {%4,%5,%6,%7}, {%8,%9}, {%0,%1,%2,%3};\n"
                        : "+f"(acc[mi][ni][0]), "+f"(acc[mi][ni][1]),
                          "+f"(acc[mi][ni][2]), "+f"(acc[mi][ni][3])
                        : "r"(a4[s][mi].x), "r"(a4[s][mi].y),
                          "r"(a4[s][mi].z), "r"(a4[s][mi].w),
                          "r"(bx), "r"(by));
                }
    }

    // epilogue
    const int gr = lane >> 2;
    const int gc = (lane & 3) * 2;
#pragma unroll
    for (int mi = 0; mi < 2; mi++) {
        int r0 = blockIdx.y * 128 + wm * 32 + mi * 16 + gr;
#pragma unroll
        for (int ni = 0; ni < 8; ni++) {
            int c0 = blockIdx.x * 128 + wn * 64 + ni * 8 + gc;
            float b0 = 0.0f, b1 = 0.0f;
            if (bias) {
                if (!GUARD_N || c0 < Nvalid) b0 = bias[c0];
                if (!GUARD_N || c0 + 1 < Nvalid) b1 = bias[c0 + 1];
            }
            float* Cp0 = C + (size_t)r0 * ldC + c0;
            float* Cp1 = C + (size_t)(r0 + 8) * ldC + c0;
            if (!GUARD_N || c0 < Nvalid) {
                Cp0[0] = acc[mi][ni][0] + b0;
                Cp1[0] = acc[mi][ni][2] + b0;
            }
            if (!GUARD_N || c0 + 1 < Nvalid) {
                Cp0[1] = acc[mi][ni][1] + b1;
                Cp1[1] = acc[mi][ni][3] + b1;
            }
        }
    }
}

// ---------------------------------------------------------------------------
// SRU scan
// ---------------------------------------------------------------------------
__global__ void sru_scan_kernel(const float* __restrict__ U,
                                float* __restrict__ h,
                                const float* __restrict__ bf,
                                const float* __restrict__ br,
                                float* __restrict__ c_out) {
    int idx = blockIdx.x * blockDim.x + threadIdx.x;
    int b = idx / H_DIM;
    int hh = idx - b * H_DIM;
    float bfv = bf[hh];
    float brv = br[hh];
    float c = 0.0f;

    const float* Ub = U + (size_t)b * N_SRU + hh;
    float* hb = h + (size_t)b * H_DIM + hh;

    for (int t = 0; t < T_DIM; t++) {
        const float* Ut = Ub + (size_t)t * B_DIM * N_SRU;
        float z = Ut[0];
        float fp = Ut[H_DIM];
        float rp = Ut[2 * H_DIM];
        float f = 1.0f / (1.0f + __expf(-(fp + bfv)));
        float r = 1.0f / (1.0f + __expf(-(rp + brv)));
        c = f * c + (1.0f - f) * z;
        float* hp = hb + (size_t)t * B_DIM * H_DIM;
        float hin = *hp;
        *hp = f2tf32f(r * c + (1.0f - r) * hin);
    }
    c_out[idx] = c;
}

// ---------------------------------------------------------------------------
// Launch
// ---------------------------------------------------------------------------
extern "C" void kernel_launch(void* const* d_in, const int* in_sizes, int n_in,
                              void* d_out, int out_size) {
    const float* x     = (const float*)d_in[0];
    const float* W1    = (const float*)d_in[2];
    const float* b1    = (const float*)d_in[3];
    const float* W_sru = (const float*)d_in[4];
    const float* bf    = (const float*)d_in[5];
    const float* br    = (const float*)d_in[6];
    const float* W3    = (const float*)d_in[7];
    const float* b3    = (const float*)d_in[8];
    float* out = (float*)d_out;

    float *h_buf, *U_buf, *WTf, *W3Tf;
    uint4* Af;
    cudaGetSymbolAddress((void**)&h_buf, g_h);
    cudaGetSymbolAddress((void**)&U_buf, g_U);
    cudaGetSymbolAddress((void**)&Af, g_Af);
    cudaGetSymbolAddress((void**)&WTf, g_WT);
    cudaGetSymbolAddress((void**)&W3Tf, g_W3T);
    uint4* BF = (uint4*)WTf;
    uint4* BF3 = (uint4*)W3Tf;
    const size_t bfLayerStride = (size_t)(N_SRU / 8) * KPCNT * 32;  // uint4 elems

    // prep B fragments
    {
        const int N8 = N_SRU / 8;                  // 384
        int blocks = N8 * KPCNT / 8;               // 3072
        for (int l = 0; l < L_DIM; l++)
            wfrag_kernel<<<blocks, 256>>>(W_sru + (size_t)l * H_DIM * N_SRU,
                                          BF + l * bfLayerStride, N_SRU, N8);
        const int N83 = N3PAD / 8;                 // 144
        wfrag_kernel<<<N83 * KPCNT / 8, 256>>>(W3, BF3, OUT_DIM, N83);
    }

    dense1_kernel<<<M_ALL, 256>>>(x, W1, b1, h_buf);

    dim3 agrid(M_ALL / 64, H_DIM / 32);            // 512 x 32
    afrag_kernel<<<agrid, 256>>>(h_buf, Af);

    float* c_base = out + (size_t)M_ALL * OUT_DIM;
    for (int l = 0; l < L_DIM; l++) {
        dim3 grid(N_SRU / 128, M_ALL / 128);
        tf32_gemm<false><<<grid, 256>>>(
            Af, BF + l * bfLayerStride, U_buf, N_SRU, N_SRU, nullptr);
        sru_scan_kernel<<<(B_DIM * H_DIM) / 256, 256>>>(
            U_buf, h_buf, bf + l * H_DIM, br + l * H_DIM,
            c_base + (size_t)l * B_DIM * H_DIM);
        afrag_kernel<<<agrid, 256>>>(h_buf, Af);
    }

    dim3 grid3(N3PAD / 128, M_ALL / 128);
    tf32_gemm<true><<<grid3, 256>>>(Af, BF3, out, OUT_DIM, OUT_DIM, b3);
}